// round 3
// baseline (speedup 1.0000x reference)
#include <cuda_runtime.h>
#include <math.h>
#include <stdint.h>

// Problem dims
#define BB   128
#define SS   256
#define DD   256
#define HH   6
#define HSD  42          // head size
#define DFF  1024
#define ROWS (BB * SS)   // 32768

// ---------------------------------------------------------------------------
// Scratch (device globals — no allocation allowed)
// ---------------------------------------------------------------------------
__device__ float g_Wpack[256 * 768];                 // [D, 3*256] q|k|v packed, zero-padded per 256-block
__device__ float g_Wprojp[256 * 256];                // Wproj zero-padded K 252->256
__device__ float g_qkv[(size_t)ROWS * 768];          // [rows, 768]: q@0, k@256, v@512 (h*42 within)
__device__ float g_hc[(size_t)ROWS * 256];           // head concat, cols 252..255 zero
__device__ float g_attn[(size_t)ROWS * 256];
__device__ float g_ln1[(size_t)ROWS * 256];
__device__ float g_ff1[(size_t)ROWS * 1024];
__device__ float g_ff2[(size_t)ROWS * 256];

// ---------------------------------------------------------------------------
// tf32 helpers
// ---------------------------------------------------------------------------
__device__ __forceinline__ float to_tf32(float x) {
    uint32_t r;
    asm("cvt.rna.tf32.f32 %0, %1;" : "=r"(r) : "f"(x));
    return __uint_as_float(r);
}

__device__ __forceinline__ void mma_tf32(float& d0, float& d1, float& d2, float& d3,
                                         uint32_t a0, uint32_t a1, uint32_t a2, uint32_t a3,
                                         uint32_t b0, uint32_t b1) {
    asm volatile(
        "mma.sync.aligned.m16n8k8.row.col.f32.tf32.tf32.f32 "
        "{%0,%1,%2,%3}, {%4,%5,%6,%7}, {%8,%9}, {%0,%1,%2,%3};\n"
        : "+f"(d0), "+f"(d1), "+f"(d2), "+f"(d3)
        : "r"(a0), "r"(a1), "r"(a2), "r"(a3), "r"(b0), "r"(b1));
}

// ---------------------------------------------------------------------------
// Weight packing
// ---------------------------------------------------------------------------
__global__ void pack_qkv_kernel(const float* __restrict__ Wq,
                                const float* __restrict__ Wk,
                                const float* __restrict__ Wv) {
    int i = blockIdx.x * 256 + threadIdx.x;          // over 256*768
    int k = i / 768, c = i - k * 768;
    int t = c >> 8, cc = c & 255;
    float v = 0.f;
    if (cc < HH * HSD) {
        int h = cc / HSD, d = cc - h * HSD;
        const float* W = (t == 0) ? Wq : (t == 1) ? Wk : Wv;
        v = W[(h * 256 + k) * HSD + d];              // [H, D, HS]
    }
    g_Wpack[i] = v;
}

__global__ void pack_proj_kernel(const float* __restrict__ Wproj) {
    int i = blockIdx.x * 256 + threadIdx.x;          // over 256*256
    int k = i >> 8, n = i & 255;
    g_Wprojp[i] = (k < 252) ? Wproj[k * 256 + n] : 0.f;
}

__global__ void zero_pad_hc_kernel() {
    int i = blockIdx.x * 256 + threadIdx.x;          // over ROWS*4
    int row = i >> 2, c = 252 + (i & 3);
    g_hc[(size_t)row * 256 + c] = 0.f;
}

// ---------------------------------------------------------------------------
// TF32 tensor-core GEMM: C[M,N] = A[M,K] @ B[K,N] (+bias)(+relu).
// Requires M%128==0, N%128==0, K%32==0 (guaranteed by padding).
// Block tile 128x128, BK=32, 256 threads = 8 warps (2x4), warp tile 64x32.
// Staging (fixed): A 128x32 via 4 float4/thread (rows tid>>3 + r*32);
//                  B 32x128 via 4 float4/thread (rows tid>>5 + r*8).
// Fragment smem pads chosen for conflict-free gathers:
//   A pad 36 -> bank (4g+c)%32 distinct;  B pad 136 -> bank (8c+g)%32 distinct.
// ---------------------------------------------------------------------------
#define PAD_A 36
#define PAD_B 136

template <bool BIAS, bool RELU>
__global__ __launch_bounds__(256, 2) void tf32_gemm_kernel(
    const float* __restrict__ A, const float* __restrict__ Bm,
    const float* __restrict__ bias, float* __restrict__ C,
    int K, int lda, int ldb, int ldc)
{
    __shared__ float As[128 * PAD_A];   // [m][k], 18.0 KB
    __shared__ float Bs[32 * PAD_B];    // [k][n], 17.0 KB

    const int tid = threadIdx.x;
    const int bm = blockIdx.y * 128, bn = blockIdx.x * 128;
    const int warp = tid >> 5, lane = tid & 31;
    const int wm = (warp >> 2) * 64;    // warp m-offset (0/64)
    const int wn = (warp & 3) * 32;     // warp n-offset (0/32/64/96)
    const int g = lane >> 2;            // groupID 0..7
    const int c = lane & 3;             // threadID in group 0..3

    // staging indices (exact tile coverage)
    const int a_row = tid >> 3;          // 0..31, +r*32 -> 128 rows
    const int a_col = (tid & 7) * 4;     // 0..28  -> 32 cols
    const int b_row = tid >> 5;          // 0..7,  +r*8 -> 32 rows
    const int b_col = (tid & 31) * 4;    // 0..124 -> 128 cols

    float d[4][4][4];
#pragma unroll
    for (int i = 0; i < 4; i++)
#pragma unroll
        for (int j = 0; j < 4; j++)
#pragma unroll
            for (int r = 0; r < 4; r++) d[i][j][r] = 0.f;

    for (int k0 = 0; k0 < K; k0 += 32) {
        float4 av[4], bv[4];
#pragma unroll
        for (int r = 0; r < 4; r++)
            av[r] = *(const float4*)(A + (size_t)(bm + a_row + r * 32) * lda + k0 + a_col);
#pragma unroll
        for (int r = 0; r < 4; r++)
            bv[r] = *(const float4*)(Bm + (size_t)(k0 + b_row + r * 8) * ldb + bn + b_col);

        __syncthreads();   // previous tile fully consumed
#pragma unroll
        for (int r = 0; r < 4; r++) {
            float* p = As + (a_row + r * 32) * PAD_A + a_col;
            p[0] = to_tf32(av[r].x); p[1] = to_tf32(av[r].y);
            p[2] = to_tf32(av[r].z); p[3] = to_tf32(av[r].w);
        }
#pragma unroll
        for (int r = 0; r < 4; r++) {
            float* p = Bs + (b_row + r * 8) * PAD_B + b_col;
            p[0] = to_tf32(bv[r].x); p[1] = to_tf32(bv[r].y);
            p[2] = to_tf32(bv[r].z); p[3] = to_tf32(bv[r].w);
        }
        __syncthreads();

#pragma unroll
        for (int ks = 0; ks < 4; ks++) {
            uint32_t af[4][4];
#pragma unroll
            for (int mt = 0; mt < 4; mt++) {
                const float* ap = As + (wm + mt * 16 + g) * PAD_A + ks * 8 + c;
                af[mt][0] = __float_as_uint(ap[0]);
                af[mt][1] = __float_as_uint(ap[8 * PAD_A]);
                af[mt][2] = __float_as_uint(ap[4]);
                af[mt][3] = __float_as_uint(ap[8 * PAD_A + 4]);
            }
            uint32_t bf[4][2];
#pragma unroll
            for (int nt = 0; nt < 4; nt++) {
                const float* bp = Bs + (ks * 8 + c) * PAD_B + wn + nt * 8 + g;
                bf[nt][0] = __float_as_uint(bp[0]);
                bf[nt][1] = __float_as_uint(bp[4 * PAD_B]);
            }
#pragma unroll
            for (int mt = 0; mt < 4; mt++)
#pragma unroll
                for (int nt = 0; nt < 4; nt++)
                    mma_tf32(d[mt][nt][0], d[mt][nt][1], d[mt][nt][2], d[mt][nt][3],
                             af[mt][0], af[mt][1], af[mt][2], af[mt][3],
                             bf[nt][0], bf[nt][1]);
        }
    }

    // epilogue: c0 (g, 2c), c1 (g, 2c+1), c2 (g+8, 2c), c3 (g+8, 2c+1)
#pragma unroll
    for (int nt = 0; nt < 4; nt++) {
        const int col = bn + wn + nt * 8 + 2 * c;
        float bx = 0.f, by = 0.f;
        if (BIAS) { bx = bias[col]; by = bias[col + 1]; }
#pragma unroll
        for (int mt = 0; mt < 4; mt++) {
            const int row = bm + wm + mt * 16 + g;
            float2 v0, v1;
            v0.x = d[mt][nt][0] + bx; v0.y = d[mt][nt][1] + by;
            v1.x = d[mt][nt][2] + bx; v1.y = d[mt][nt][3] + by;
            if (RELU) {
                v0.x = fmaxf(v0.x, 0.f); v0.y = fmaxf(v0.y, 0.f);
                v1.x = fmaxf(v1.x, 0.f); v1.y = fmaxf(v1.y, 0.f);
            }
            *(float2*)(C + (size_t)row * ldc + col)       = v0;
            *(float2*)(C + (size_t)(row + 8) * ldc + col) = v1;
        }
    }
}

// ---------------------------------------------------------------------------
// Causal attention: one block per (h, b); thread s owns query row s.
// K/V staged in smem (broadcast reads). Online softmax with deferred rescale.
// ---------------------------------------------------------------------------
__global__ void attn_kernel() {
    extern __shared__ float sm[];
    float* Ksm = sm;                 // 256*42
    float* Vsm = sm + 256 * 42;      // 256*42

    const int h = blockIdx.x;
    const int b = blockIdx.y;
    const int s = threadIdx.x;
    const float* base = g_qkv + (size_t)b * 256 * 768;

    for (int i = s; i < 256 * 42; i += 256) {
        int t = i / 42, d = i - t * 42;
        const float* src = base + (size_t)t * 768 + h * 42 + d;
        Ksm[i] = src[256];
        Vsm[i] = src[512];
    }

    float2 qv[21];
    {
        const float* qp = base + (size_t)s * 768 + h * 42;
#pragma unroll
        for (int j = 0; j < 21; j++) { qv[j].x = qp[2 * j]; qv[j].y = qp[2 * j + 1]; }
    }
    __syncthreads();

    float m = -1e30f, l = 0.f;
    float acc[42];
#pragma unroll
    for (int d = 0; d < 42; d++) acc[d] = 0.f;

    const float scale = 0.15430334996209191f;        // 1/sqrt(42)
    const int tmax = s | 31;                         // warp-uniform causal bound

    for (int t = 0; t <= tmax; t++) {
        const float2* kr = (const float2*)(Ksm + t * 42);
        float dot = 0.f;
#pragma unroll
        for (int j = 0; j < 21; j++) {
            float2 kk = kr[j];
            dot += qv[j].x * kk.x;
            dot += qv[j].y * kk.y;
        }
        float x = (t <= s) ? dot * scale : -1e30f;
        if (x > m) {                                  // deferred rescale
            float corr = __expf(m - x);
            l *= corr;
#pragma unroll
            for (int d = 0; d < 42; d++) acc[d] *= corr;
            m = x;
        }
        float p = __expf(x - m);                      // masked lanes: exp(-huge)=0
        l += p;
        const float2* vr = (const float2*)(Vsm + t * 42);
#pragma unroll
        for (int j = 0; j < 21; j++) {
            float2 vv = vr[j];
            acc[2 * j]     += p * vv.x;
            acc[2 * j + 1] += p * vv.y;
        }
    }

    float inv = 1.f / l;
    float* out = g_hc + (size_t)(b * 256 + s) * 256 + h * 42;
#pragma unroll
    for (int d = 0; d < 42; d++) out[d] = acc[d] * inv;
}

// ---------------------------------------------------------------------------
// Residual + LayerNorm over D=256. Warp per row, 8 elems per lane.
// ---------------------------------------------------------------------------
__global__ void ln_kernel(const float* __restrict__ X, const float* __restrict__ R,
                          const float* __restrict__ gam, const float* __restrict__ bet,
                          float* __restrict__ out) {
    const int lane = threadIdx.x & 31;
    const int warp = threadIdx.x >> 5;
    const size_t row = (size_t)blockIdx.x * 8 + warp;

    const float4* xp = (const float4*)(X + row * 256);
    const float4* rp = (const float4*)(R + row * 256);
    float4 x0 = xp[lane * 2],     r0 = rp[lane * 2];
    float4 x1 = xp[lane * 2 + 1], r1 = rp[lane * 2 + 1];

    float v[8];
    v[0] = x0.x + r0.x; v[1] = x0.y + r0.y; v[2] = x0.z + r0.z; v[3] = x0.w + r0.w;
    v[4] = x1.x + r1.x; v[5] = x1.y + r1.y; v[6] = x1.z + r1.z; v[7] = x1.w + r1.w;

    float sum = 0.f;
#pragma unroll
    for (int j = 0; j < 8; j++) sum += v[j];
#pragma unroll
    for (int o = 16; o > 0; o >>= 1) sum += __shfl_xor_sync(0xffffffffu, sum, o);
    float mu = sum * (1.f / 256.f);

    float vs = 0.f;
#pragma unroll
    for (int j = 0; j < 8; j++) { float dd = v[j] - mu; vs += dd * dd; }
#pragma unroll
    for (int o = 16; o > 0; o >>= 1) vs += __shfl_xor_sync(0xffffffffu, vs, o);
    float rstd = rsqrtf(vs * (1.f / 256.f) + 1e-5f);

    const float4* gp = (const float4*)gam;
    const float4* bp = (const float4*)bet;
    float4 g0 = gp[lane * 2], g1 = gp[lane * 2 + 1];
    float4 b0 = bp[lane * 2], b1 = bp[lane * 2 + 1];

    float4 o0, o1;
    o0.x = (v[0] - mu) * rstd * g0.x + b0.x;
    o0.y = (v[1] - mu) * rstd * g0.y + b0.y;
    o0.z = (v[2] - mu) * rstd * g0.z + b0.z;
    o0.w = (v[3] - mu) * rstd * g0.w + b0.w;
    o1.x = (v[4] - mu) * rstd * g1.x + b1.x;
    o1.y = (v[5] - mu) * rstd * g1.y + b1.y;
    o1.z = (v[6] - mu) * rstd * g1.z + b1.z;
    o1.w = (v[7] - mu) * rstd * g1.w + b1.w;

    float4* op = (float4*)(out + row * 256);
    op[lane * 2]     = o0;
    op[lane * 2 + 1] = o1;
}

// ---------------------------------------------------------------------------
// Launch
// ---------------------------------------------------------------------------
extern "C" void kernel_launch(void* const* d_in, const int* in_sizes, int n_in,
                              void* d_out, int out_size) {
    const float* x     = (const float*)d_in[0];
    const float* Wq    = (const float*)d_in[1];
    const float* Wk    = (const float*)d_in[2];
    const float* Wv    = (const float*)d_in[3];
    const float* Wproj = (const float*)d_in[4];
    const float* bproj = (const float*)d_in[5];
    const float* ln1g  = (const float*)d_in[6];
    const float* ln1b  = (const float*)d_in[7];
    const float* W1    = (const float*)d_in[8];
    const float* b1    = (const float*)d_in[9];
    const float* W2    = (const float*)d_in[10];
    const float* b2    = (const float*)d_in[11];
    const float* ln2g  = (const float*)d_in[12];
    const float* ln2b  = (const float*)d_in[13];
    float* out = (float*)d_out;

    float *pWpack, *pWprojp, *pqkv, *phc, *pattn, *pln1, *pff1, *pff2;
    cudaGetSymbolAddress((void**)&pWpack,  g_Wpack);
    cudaGetSymbolAddress((void**)&pWprojp, g_Wprojp);
    cudaGetSymbolAddress((void**)&pqkv,    g_qkv);
    cudaGetSymbolAddress((void**)&phc,     g_hc);
    cudaGetSymbolAddress((void**)&pattn,   g_attn);
    cudaGetSymbolAddress((void**)&pln1,    g_ln1);
    cudaGetSymbolAddress((void**)&pff1,    g_ff1);
    cudaGetSymbolAddress((void**)&pff2,    g_ff2);

    cudaFuncSetAttribute(attn_kernel, cudaFuncAttributeMaxDynamicSharedMemorySize,
                         2 * 256 * 42 * (int)sizeof(float));

    // 1. pack weights
    pack_qkv_kernel<<<768, 256>>>(Wq, Wk, Wv);
    pack_proj_kernel<<<256, 256>>>(Wproj);
    zero_pad_hc_kernel<<<512, 256>>>();

    // 2. QKV projection: [32768,256] @ [256,768] -> [32768,768]
    tf32_gemm_kernel<false, false><<<dim3(6, 256), 256>>>(x, pWpack, nullptr, pqkv,
                                                          256, 256, 768, 768);

    // 3. causal attention -> head concat [32768, 256(pad)]
    attn_kernel<<<dim3(HH, BB), 256, 2 * 256 * 42 * sizeof(float)>>>();

    // 4. output projection: [32768,256] @ [256,256] + bproj
    tf32_gemm_kernel<true, false><<<dim3(2, 256), 256>>>(phc, pWprojp, bproj, pattn,
                                                         256, 256, 256, 256);

    // 5. residual + LN1
    ln_kernel<<<ROWS / 8, 256>>>(x, pattn, ln1g, ln1b, pln1);

    // 6. FFN1: [32768,256] @ [256,1024] + b1, relu
    tf32_gemm_kernel<true, true><<<dim3(8, 256), 256>>>(pln1, W1, b1, pff1,
                                                        256, 256, 1024, 1024);

    // 7. FFN2: [32768,1024] @ [1024,256] + b2
    tf32_gemm_kernel<true, false><<<dim3(2, 256), 256>>>(pff1, W2, b2, pff2,
                                                         1024, 1024, 256, 256);

    // 8. residual + LN2 -> output
    ln_kernel<<<ROWS / 8, 256>>>(pln1, pff2, ln2g, ln2b, out);
}

// round 15
// speedup vs baseline: 1.4727x; 1.4727x over previous
#include <cuda_runtime.h>
#include <math.h>
#include <stdint.h>

// Problem dims
#define BB   128
#define SS   256
#define DD   256
#define HH   6
#define HSD  42          // head size
#define DFF  1024
#define ROWS (BB * SS)   // 32768

// ---------------------------------------------------------------------------
// Scratch (device globals — no allocation allowed)
// ---------------------------------------------------------------------------
__device__ float g_Wpack[256 * 768];                 // [D, 3*256] q|k|v packed, zero-padded per 256-block
__device__ float g_Wprojp[256 * 256];                // Wproj zero-padded K 252->256
__device__ float g_qkv[(size_t)ROWS * 768];          // [rows, 768]: q@0, k@256, v@512 (h*42 within)
__device__ float g_hc[(size_t)ROWS * 256];           // head concat, cols 252..255 zero
__device__ float g_attn[(size_t)ROWS * 256];
__device__ float g_ln1[(size_t)ROWS * 256];
__device__ float g_ff1[(size_t)ROWS * 1024];
__device__ float g_ff2[(size_t)ROWS * 256];

// ---------------------------------------------------------------------------
// helpers
// ---------------------------------------------------------------------------
__device__ __forceinline__ void mma_tf32(float& d0, float& d1, float& d2, float& d3,
                                         uint32_t a0, uint32_t a1, uint32_t a2, uint32_t a3,
                                         uint32_t b0, uint32_t b1) {
    asm volatile(
        "mma.sync.aligned.m16n8k8.row.col.f32.tf32.tf32.f32 "
        "{%0,%1,%2,%3}, {%4,%5,%6,%7}, {%8,%9}, {%0,%1,%2,%3};\n"
        : "+f"(d0), "+f"(d1), "+f"(d2), "+f"(d3)
        : "r"(a0), "r"(a1), "r"(a2), "r"(a3), "r"(b0), "r"(b1));
}

__device__ __forceinline__ void cp_async16(uint32_t smem_addr, const void* gptr) {
    asm volatile("cp.async.cg.shared.global [%0], [%1], 16;\n"
                 :: "r"(smem_addr), "l"(gptr));
}
__device__ __forceinline__ void cp_commit() {
    asm volatile("cp.async.commit_group;\n");
}
template <int N>
__device__ __forceinline__ void cp_wait() {
    asm volatile("cp.async.wait_group %0;\n" :: "n"(N));
}

// ---------------------------------------------------------------------------
// Weight packing
// ---------------------------------------------------------------------------
__global__ void pack_qkv_kernel(const float* __restrict__ Wq,
                                const float* __restrict__ Wk,
                                const float* __restrict__ Wv) {
    int i = blockIdx.x * 256 + threadIdx.x;          // over 256*768
    int k = i / 768, c = i - k * 768;
    int t = c >> 8, cc = c & 255;
    float v = 0.f;
    if (cc < HH * HSD) {
        int h = cc / HSD, d = cc - h * HSD;
        const float* W = (t == 0) ? Wq : (t == 1) ? Wk : Wv;
        v = W[(h * 256 + k) * HSD + d];              // [H, D, HS]
    }
    g_Wpack[i] = v;
}

__global__ void pack_proj_kernel(const float* __restrict__ Wproj) {
    int i = blockIdx.x * 256 + threadIdx.x;          // over 256*256
    int k = i >> 8, n = i & 255;
    g_Wprojp[i] = (k < 252) ? Wproj[k * 256 + n] : 0.f;
}

__global__ void zero_pad_hc_kernel() {
    int i = blockIdx.x * 256 + threadIdx.x;          // over ROWS*4
    int row = i >> 2, c = 252 + (i & 3);
    g_hc[(size_t)row * 256 + c] = 0.f;
}

// ---------------------------------------------------------------------------
// TF32 tensor-core GEMM, 3-stage cp.async pipeline. (audited; see R4 notes)
// ---------------------------------------------------------------------------
#define PAD_A 36
#define PAD_B 136
#define GSTAGES 3
#define STAGE_FLOATS (128 * PAD_A + 32 * PAD_B)      // 8960 floats = 35840 B
#define GEMM_SMEM (GSTAGES * STAGE_FLOATS * 4)       // 107520 B

template <bool BIAS, bool RELU>
__global__ __launch_bounds__(256, 2) void tf32_gemm_kernel(
    const float* __restrict__ A, const float* __restrict__ Bm,
    const float* __restrict__ bias, float* __restrict__ C,
    int K, int lda, int ldb, int ldc)
{
    extern __shared__ float smem[];

    const int tid = threadIdx.x;
    const int bm = blockIdx.y * 128, bn = blockIdx.x * 128;
    const int warp = tid >> 5, lane = tid & 31;
    const int wm = (warp >> 2) * 64;
    const int wn = (warp & 3) * 32;
    const int g = lane >> 2;
    const int c = lane & 3;

    const int a_row = tid >> 3;          // 0..31, +r*32 -> 128 rows
    const int a_col = (tid & 7) * 4;     // 0..28  -> 32 cols
    const int b_row = tid >> 5;          // 0..7,  +r*8 -> 32 rows
    const int b_col = (tid & 31) * 4;    // 0..124 -> 128 cols

    const float* Abase = A + (size_t)(bm + a_row) * lda + a_col;
    const float* Bbase = Bm + (size_t)b_row * ldb + bn + b_col;

    const uint32_t smem_base = (uint32_t)__cvta_generic_to_shared(smem);
    const uint32_t sA_off = (a_row * PAD_A + a_col) * 4;
    const uint32_t sB_off = (128 * PAD_A + b_row * PAD_B + b_col) * 4;

    const int nIters = K >> 5;

    auto load_stage = [&](int it) {
        if (it < nIters) {
            const int k0 = it << 5;
            const uint32_t sbase = smem_base + (uint32_t)(it % GSTAGES) * (STAGE_FLOATS * 4);
#pragma unroll
            for (int r = 0; r < 4; r++)
                cp_async16(sbase + sA_off + r * (32 * PAD_A * 4),
                           Abase + (size_t)r * 32 * lda + k0);
#pragma unroll
            for (int r = 0; r < 4; r++)
                cp_async16(sbase + sB_off + r * (8 * PAD_B * 4),
                           Bbase + (size_t)(k0 + r * 8) * ldb);
        }
        cp_commit();
    };

    float d[4][4][4];
#pragma unroll
    for (int i = 0; i < 4; i++)
#pragma unroll
        for (int j = 0; j < 4; j++)
#pragma unroll
            for (int r = 0; r < 4; r++) d[i][j][r] = 0.f;

    load_stage(0);
    load_stage(1);

    for (int it = 0; it < nIters; it++) {
        cp_wait<GSTAGES - 2>();
        __syncthreads();
        load_stage(it + GSTAGES - 1);

        const float* As = smem + (it % GSTAGES) * STAGE_FLOATS;
        const float* Bs = As + 128 * PAD_A;

#pragma unroll
        for (int ks = 0; ks < 4; ks++) {
            uint32_t af[4][4];
#pragma unroll
            for (int mt = 0; mt < 4; mt++) {
                const float* ap = As + (wm + mt * 16 + g) * PAD_A + ks * 8 + c;
                af[mt][0] = __float_as_uint(ap[0]);
                af[mt][1] = __float_as_uint(ap[8 * PAD_A]);
                af[mt][2] = __float_as_uint(ap[4]);
                af[mt][3] = __float_as_uint(ap[8 * PAD_A + 4]);
            }
            uint32_t bf[4][2];
#pragma unroll
            for (int nt = 0; nt < 4; nt++) {
                const float* bp = Bs + (ks * 8 + c) * PAD_B + wn + nt * 8 + g;
                bf[nt][0] = __float_as_uint(bp[0]);
                bf[nt][1] = __float_as_uint(bp[4 * PAD_B]);
            }
#pragma unroll
            for (int mt = 0; mt < 4; mt++)
#pragma unroll
                for (int nt = 0; nt < 4; nt++)
                    mma_tf32(d[mt][nt][0], d[mt][nt][1], d[mt][nt][2], d[mt][nt][3],
                             af[mt][0], af[mt][1], af[mt][2], af[mt][3],
                             bf[nt][0], bf[nt][1]);
        }
    }

#pragma unroll
    for (int nt = 0; nt < 4; nt++) {
        const int col = bn + wn + nt * 8 + 2 * c;
        float bx = 0.f, by = 0.f;
        if (BIAS) { bx = bias[col]; by = bias[col + 1]; }
#pragma unroll
        for (int mt = 0; mt < 4; mt++) {
            const int row = bm + wm + mt * 16 + g;
            float2 v0, v1;
            v0.x = d[mt][nt][0] + bx; v0.y = d[mt][nt][1] + by;
            v1.x = d[mt][nt][2] + bx; v1.y = d[mt][nt][3] + by;
            if (RELU) {
                v0.x = fmaxf(v0.x, 0.f); v0.y = fmaxf(v0.y, 0.f);
                v1.x = fmaxf(v1.x, 0.f); v1.y = fmaxf(v1.y, 0.f);
            }
            *(float2*)(C + (size_t)row * ldc + col)       = v0;
            *(float2*)(C + (size_t)(row + 8) * ldc + col) = v1;
        }
    }
}

// ---------------------------------------------------------------------------
// Tensor-core causal flash attention. One block per (h, b), 8 warps.
// Warp w owns query rows [w*32, w*32+32); loops over its causal 64-key tiles.
// K smem [256][52] (d 42..51 zero), V smem [256][56] (d 42..55 zero),
// per-warp P scratch [32][68]. All fragment patterns identical to the
// R3-validated GEMM mma layout.
// ---------------------------------------------------------------------------
#define KP 52
#define VP 56
#define PP 68
#define ATTN_SMEM ((256 * KP + 256 * VP + 8 * 32 * PP) * 4)   // 180224 B

__global__ __launch_bounds__(256, 1) void attn_mma_kernel() {
    extern __shared__ float sm[];
    float* Ksm = sm;                      // [256][52]
    float* Vsm = sm + 256 * KP;           // [256][56]
    float* Psm = sm + 256 * (KP + VP);    // 8 x [32][68]

    const int h = blockIdx.x, b = blockIdx.y;
    const int tid = threadIdx.x;
    const int w = tid >> 5, lane = tid & 31;
    const int g = lane >> 2, c = lane & 3;
    const float* base = g_qkv + (size_t)b * 256 * 768;

    // stage K,V (+ zero pads protect padded head-dim products)
    for (int i = tid; i < 256 * 42; i += 256) {
        int t = i / 42, d = i - t * 42;
        const float* src = base + (size_t)t * 768 + h * 42 + d;
        Ksm[t * KP + d] = src[256];
        Vsm[t * VP + d] = src[512];
    }
    for (int i = tid; i < 256 * 10; i += 256) { int t = i / 10; Ksm[t * KP + 42 + i % 10] = 0.f; }
    for (int i = tid; i < 256 * 14; i += 256) { int t = i / 14; Vsm[t * VP + 42 + i % 14] = 0.f; }
    __syncthreads();

    // preload Q fragments (A operand): rows w*32+mt*16+{g,g+8}, k=ks*8+{c,c+4}.
    // d>=42 reads garbage within the row (finite) — multiplied by Ksm zero pad.
    uint32_t qf[2][6][4];
    {
        const float* qb = base + h * 42;
#pragma unroll
        for (int mt = 0; mt < 2; mt++) {
            int r0 = w * 32 + mt * 16 + g;
#pragma unroll
            for (int ks = 0; ks < 6; ks++) {
                int d0 = ks * 8 + c;
                qf[mt][ks][0] = __float_as_uint(qb[(size_t)r0 * 768 + d0]);
                qf[mt][ks][1] = __float_as_uint(qb[(size_t)(r0 + 8) * 768 + d0]);
                qf[mt][ks][2] = __float_as_uint(qb[(size_t)r0 * 768 + d0 + 4]);
                qf[mt][ks][3] = __float_as_uint(qb[(size_t)(r0 + 8) * 768 + d0 + 4]);
            }
        }
    }

    // per-thread row slots: i = mt*2 + rh, rows w*32 + mt*16 + g + rh*8
    float m_[4], l_[4];
#pragma unroll
    for (int i = 0; i < 4; i++) { m_[i] = -1e30f; l_[i] = 0.f; }
    float oacc[2][6][4];
#pragma unroll
    for (int mt = 0; mt < 2; mt++)
#pragma unroll
        for (int nt = 0; nt < 6; nt++)
#pragma unroll
            for (int r = 0; r < 4; r++) oacc[mt][nt][r] = 0.f;

    float* Ps = Psm + w * 32 * PP;
    const int ntiles = (w * 32 + 31) / 64 + 1;
    const float scale = 0.15430334996209191f;     // 1/sqrt(42)

    for (int kt = 0; kt < ntiles; kt++) {
        // ---- S = Q K^T over this key tile ----
        float sacc[2][8][4];
#pragma unroll
        for (int mt = 0; mt < 2; mt++)
#pragma unroll
            for (int nt = 0; nt < 8; nt++)
#pragma unroll
                for (int r = 0; r < 4; r++) sacc[mt][nt][r] = 0.f;

#pragma unroll
        for (int ks = 0; ks < 6; ks++) {
#pragma unroll
            for (int nt = 0; nt < 8; nt++) {
                const float* kp_ = Ksm + (kt * 64 + nt * 8 + g) * KP + ks * 8 + c;
                uint32_t b0 = __float_as_uint(kp_[0]);
                uint32_t b1 = __float_as_uint(kp_[4]);
#pragma unroll
                for (int mt = 0; mt < 2; mt++)
                    mma_tf32(sacc[mt][nt][0], sacc[mt][nt][1], sacc[mt][nt][2], sacc[mt][nt][3],
                             qf[mt][ks][0], qf[mt][ks][1], qf[mt][ks][2], qf[mt][ks][3],
                             b0, b1);
            }
        }

        // ---- scale + causal mask + online softmax ----
        float tmax[4] = {-1e30f, -1e30f, -1e30f, -1e30f};
#pragma unroll
        for (int mt = 0; mt < 2; mt++)
#pragma unroll
            for (int nt = 0; nt < 8; nt++)
#pragma unroll
                for (int r = 0; r < 4; r++) {
                    int rh = r >> 1;
                    int qrow = w * 32 + mt * 16 + g + rh * 8;
                    int tcol = kt * 64 + nt * 8 + 2 * c + (r & 1);
                    float x = sacc[mt][nt][r] * scale;
                    if (tcol > qrow) x = -1e30f;
                    sacc[mt][nt][r] = x;
                    int i = mt * 2 + rh;
                    tmax[i] = fmaxf(tmax[i], x);
                }
#pragma unroll
        for (int i = 0; i < 4; i++) {
            tmax[i] = fmaxf(tmax[i], __shfl_xor_sync(0xffffffffu, tmax[i], 1));
            tmax[i] = fmaxf(tmax[i], __shfl_xor_sync(0xffffffffu, tmax[i], 2));
        }
        float corr[4], lsum[4];
#pragma unroll
        for (int i = 0; i < 4; i++) {
            float nm = fmaxf(m_[i], tmax[i]);
            corr[i] = __expf(m_[i] - nm);
            m_[i] = nm;
            lsum[i] = 0.f;
        }
#pragma unroll
        for (int mt = 0; mt < 2; mt++)
#pragma unroll
            for (int nt = 0; nt < 8; nt++)
#pragma unroll
                for (int r = 0; r < 4; r++) {
                    int i = mt * 2 + (r >> 1);
                    float p = __expf(sacc[mt][nt][r] - m_[i]);
                    sacc[mt][nt][r] = p;
                    lsum[i] += p;
                }
#pragma unroll
        for (int i = 0; i < 4; i++) {
            lsum[i] += __shfl_xor_sync(0xffffffffu, lsum[i], 1);
            lsum[i] += __shfl_xor_sync(0xffffffffu, lsum[i], 2);
            l_[i] = l_[i] * corr[i] + lsum[i];
        }
#pragma unroll
        for (int mt = 0; mt < 2; mt++)
#pragma unroll
            for (int nt = 0; nt < 6; nt++)
#pragma unroll
                for (int r = 0; r < 4; r++)
                    oacc[mt][nt][r] *= corr[mt * 2 + (r >> 1)];

        // ---- write P to per-warp smem (acc layout -> [m][k] layout) ----
#pragma unroll
        for (int mt = 0; mt < 2; mt++) {
            int pr = mt * 16 + g;
#pragma unroll
            for (int nt = 0; nt < 8; nt++) {
                *(float2*)&Ps[pr * PP + nt * 8 + 2 * c] =
                    make_float2(sacc[mt][nt][0], sacc[mt][nt][1]);
                *(float2*)&Ps[(pr + 8) * PP + nt * 8 + 2 * c] =
                    make_float2(sacc[mt][nt][2], sacc[mt][nt][3]);
            }
        }
        __syncwarp();

        // ---- O += P V ----
#pragma unroll
        for (int kp = 0; kp < 8; kp++) {
            uint32_t a[2][4];
#pragma unroll
            for (int mt = 0; mt < 2; mt++) {
                const float* ap = Ps + (mt * 16 + g) * PP + kp * 8 + c;
                a[mt][0] = __float_as_uint(ap[0]);
                a[mt][1] = __float_as_uint(ap[8 * PP]);
                a[mt][2] = __float_as_uint(ap[4]);
                a[mt][3] = __float_as_uint(ap[8 * PP + 4]);
            }
#pragma unroll
            for (int nt = 0; nt < 6; nt++) {
                const float* vp_ = Vsm + (kt * 64 + kp * 8 + c) * VP + nt * 8 + g;
                uint32_t b0 = __float_as_uint(vp_[0]);
                uint32_t b1 = __float_as_uint(vp_[4 * VP]);
#pragma unroll
                for (int mt = 0; mt < 2; mt++)
                    mma_tf32(oacc[mt][nt][0], oacc[mt][nt][1], oacc[mt][nt][2], oacc[mt][nt][3],
                             a[mt][0], a[mt][1], a[mt][2], a[mt][3], b0, b1);
            }
        }
        __syncwarp();    // protect Ps before next tile's overwrite
    }

    // ---- normalize + write head output ----
    float inv[4];
#pragma unroll
    for (int i = 0; i < 4; i++) inv[i] = 1.f / l_[i];
#pragma unroll
    for (int mt = 0; mt < 2; mt++)
#pragma unroll
        for (int nt = 0; nt < 6; nt++)
#pragma unroll
            for (int r = 0; r < 4; r++) {
                int rh = r >> 1;
                int col = nt * 8 + 2 * c + (r & 1);
                if (col < 42) {
                    int row = b * 256 + w * 32 + mt * 16 + g + rh * 8;
                    g_hc[(size_t)row * 256 + h * 42 + col] =
                        oacc[mt][nt][r] * inv[mt * 2 + rh];
                }
            }
}

// ---------------------------------------------------------------------------
// Residual + LayerNorm over D=256. Warp per row, 8 elems per lane.
// ---------------------------------------------------------------------------
__global__ void ln_kernel(const float* __restrict__ X, const float* __restrict__ R,
                          const float* __restrict__ gam, const float* __restrict__ bet,
                          float* __restrict__ out) {
    const int lane = threadIdx.x & 31;
    const int warp = threadIdx.x >> 5;
    const size_t row = (size_t)blockIdx.x * 8 + warp;

    const float4* xp = (const float4*)(X + row * 256);
    const float4* rp = (const float4*)(R + row * 256);
    float4 x0 = xp[lane * 2],     r0 = rp[lane * 2];
    float4 x1 = xp[lane * 2 + 1], r1 = rp[lane * 2 + 1];

    float v[8];
    v[0] = x0.x + r0.x; v[1] = x0.y + r0.y; v[2] = x0.z + r0.z; v[3] = x0.w + r0.w;
    v[4] = x1.x + r1.x; v[5] = x1.y + r1.y; v[6] = x1.z + r1.z; v[7] = x1.w + r1.w;

    float sum = 0.f;
#pragma unroll
    for (int j = 0; j < 8; j++) sum += v[j];
#pragma unroll
    for (int o = 16; o > 0; o >>= 1) sum += __shfl_xor_sync(0xffffffffu, sum, o);
    float mu = sum * (1.f / 256.f);

    float vs = 0.f;
#pragma unroll
    for (int j = 0; j < 8; j++) { float dd = v[j] - mu; vs += dd * dd; }
#pragma unroll
    for (int o = 16; o > 0; o >>= 1) vs += __shfl_xor_sync(0xffffffffu, vs, o);
    float rstd = rsqrtf(vs * (1.f / 256.f) + 1e-5f);

    const float4* gp = (const float4*)gam;
    const float4* bp = (const float4*)bet;
    float4 g0 = gp[lane * 2], g1 = gp[lane * 2 + 1];
    float4 b0 = bp[lane * 2], b1 = bp[lane * 2 + 1];

    float4 o0, o1;
    o0.x = (v[0] - mu) * rstd * g0.x + b0.x;
    o0.y = (v[1] - mu) * rstd * g0.y + b0.y;
    o0.z = (v[2] - mu) * rstd * g0.z + b0.z;
    o0.w = (v[3] - mu) * rstd * g0.w + b0.w;
    o1.x = (v[4] - mu) * rstd * g1.x + b1.x;
    o1.y = (v[5] - mu) * rstd * g1.y + b1.y;
    o1.z = (v[6] - mu) * rstd * g1.z + b1.z;
    o1.w = (v[7] - mu) * rstd * g1.w + b1.w;

    float4* op = (float4*)(out + row * 256);
    op[lane * 2]     = o0;
    op[lane * 2 + 1] = o1;
}

// ---------------------------------------------------------------------------
// Launch
// ---------------------------------------------------------------------------
extern "C" void kernel_launch(void* const* d_in, const int* in_sizes, int n_in,
                              void* d_out, int out_size) {
    const float* x     = (const float*)d_in[0];
    const float* Wq    = (const float*)d_in[1];
    const float* Wk    = (const float*)d_in[2];
    const float* Wv    = (const float*)d_in[3];
    const float* Wproj = (const float*)d_in[4];
    const float* bproj = (const float*)d_in[5];
    const float* ln1g  = (const float*)d_in[6];
    const float* ln1b  = (const float*)d_in[7];
    const float* W1    = (const float*)d_in[8];
    const float* b1    = (const float*)d_in[9];
    const float* W2    = (const float*)d_in[10];
    const float* b2    = (const float*)d_in[11];
    const float* ln2g  = (const float*)d_in[12];
    const float* ln2b  = (const float*)d_in[13];
    float* out = (float*)d_out;

    float *pWpack, *pWprojp, *pqkv, *phc, *pattn, *pln1, *pff1, *pff2;
    cudaGetSymbolAddress((void**)&pWpack,  g_Wpack);
    cudaGetSymbolAddress((void**)&pWprojp, g_Wprojp);
    cudaGetSymbolAddress((void**)&pqkv,    g_qkv);
    cudaGetSymbolAddress((void**)&phc,     g_hc);
    cudaGetSymbolAddress((void**)&pattn,   g_attn);
    cudaGetSymbolAddress((void**)&pln1,    g_ln1);
    cudaGetSymbolAddress((void**)&pff1,    g_ff1);
    cudaGetSymbolAddress((void**)&pff2,    g_ff2);

    cudaFuncSetAttribute(attn_mma_kernel, cudaFuncAttributeMaxDynamicSharedMemorySize,
                         ATTN_SMEM);
    cudaFuncSetAttribute(tf32_gemm_kernel<false, false>,
                         cudaFuncAttributeMaxDynamicSharedMemorySize, GEMM_SMEM);
    cudaFuncSetAttribute(tf32_gemm_kernel<true, false>,
                         cudaFuncAttributeMaxDynamicSharedMemorySize, GEMM_SMEM);
    cudaFuncSetAttribute(tf32_gemm_kernel<true, true>,
                         cudaFuncAttributeMaxDynamicSharedMemorySize, GEMM_SMEM);

    // 1. pack weights
    pack_qkv_kernel<<<768, 256>>>(Wq, Wk, Wv);
    pack_proj_kernel<<<256, 256>>>(Wproj);
    zero_pad_hc_kernel<<<512, 256>>>();

    // 2. QKV projection: [32768,256] @ [256,768] -> [32768,768]
    tf32_gemm_kernel<false, false><<<dim3(6, 256), 256, GEMM_SMEM>>>(
        x, pWpack, nullptr, pqkv, 256, 256, 768, 768);

    // 3. causal attention (tensor-core flash) -> head concat [32768, 256(pad)]
    attn_mma_kernel<<<dim3(HH, BB), 256, ATTN_SMEM>>>();

    // 4. output projection: [32768,256] @ [256,256] + bproj
    tf32_gemm_kernel<true, false><<<dim3(2, 256), 256, GEMM_SMEM>>>(
        phc, pWprojp, bproj, pattn, 256, 256, 256, 256);

    // 5. residual + LN1
    ln_kernel<<<ROWS / 8, 256>>>(x, pattn, ln1g, ln1b, pln1);

    // 6. FFN1: [32768,256] @ [256,1024] + b1, relu
    tf32_gemm_kernel<true, true><<<dim3(8, 256), 256, GEMM_SMEM>>>(
        pln1, W1, b1, pff1, 256, 256, 1024, 1024);

    // 7. FFN2: [32768,1024] @ [1024,256] + b2
    tf32_gemm_kernel<true, false><<<dim3(2, 256), 256, GEMM_SMEM>>>(
        pff1, W2, b2, pff2, 1024, 1024, 256, 256);

    // 8. residual + LN2 -> output
    ln_kernel<<<ROWS / 8, 256>>>(pln1, pff2, ln2g, ln2b, out);
}